// round 3
// baseline (speedup 1.0000x reference)
#include <cuda_runtime.h>

// SplitMLP R3: 2 groups per CTA, 8b x 8j thread tile, FFMA2 everywhere,
// conflict-audited smem layouts.
//   AsT[row][b]: rows 0..15 day (shared), 16..47 items g0, 49..80 items g1 (gap row 48
//   so the g1 rows land on different banks). pitch 130 floats.
//   Ws4[kq][j]: float4 = W[4kq..4kq+3][j], j 0..127 (two groups), pitch 129 float4.
//   hs[j][b]: pitch 130, group-1 rows offset +2 floats (bank shift).

#define NGRP 10000
#define PA 130            // AsT / hs pitch (floats)
#define WQ 129            // Ws4 pitch (float4 units)
#define ASZ 10532         // AsT region (81*130=10530, padded to 16B multiple)
#define USZ (ASZ + 12*WQ*4)   // 10532 + 6192 = 16724 floats

#define FMA2(d, a, b, c) \
    asm("fma.rn.f32x2 %0, %1, %2, %3;" : "=l"(d) : "l"(a), "l"(b), "l"(c))
#define PACK2(d, x) \
    asm("mov.b64 %0, {%1, %1};" : "=l"(d) : "f"(x))
#define UNPACK2(lo, hi, v) \
    asm("mov.b64 {%0, %1}, %2;" : "=f"(lo), "=f"(hi) : "l"(v))

typedef unsigned long long ull;

__global__ __launch_bounds__(256, 2)
void splitmlp_kernel(const float* __restrict__ day,
                     const float* __restrict__ items,
                     const float* __restrict__ W1d,
                     const float* __restrict__ W1v,
                     const float* __restrict__ b1,
                     const float* __restrict__ W2,
                     const float* __restrict__ b2,
                     float* __restrict__ out)
{
    __shared__ __align__(16) float u[USZ];
    __shared__ __align__(16) float W2sT[2 * 64 * 4];   // [grp][j][o]
    __shared__ float b1s[128];                         // [grp*64 + j]
    __shared__ __align__(16) float b2s[8];             // [grp][o]

    float*  AsT = u;
    float4* Ws4 = (float4*)(u + ASZ);
    float*  hs  = u;   // aliases after sync

    const int bx = blockIdx.x;
    const int t  = threadIdx.x;

    // ================= Staging =================
    // day[b][c] -> AsT[c][b]  (rows 0..15). banks: 8q+2r+b, q0..3 x b0..7 distinct.
    {
        const float4* dsrc = (const float4*)day;   // 512 float4
        #pragma unroll
        for (int i = 0; i < 2; i++) {
            int idx = t + i * 256;
            int b = idx >> 2, q = idx & 3;
            float4 v = dsrc[idx];
            AsT[(4 * q + 0) * PA + b] = v.x;
            AsT[(4 * q + 1) * PA + b] = v.y;
            AsT[(4 * q + 2) * PA + b] = v.z;
            AsT[(4 * q + 3) * PA + b] = v.w;
        }
    }
    // items[b][g][v] -> AsT rows 16+33*grp+v. Warp covers 8 b x 4 q -> banks 8q+2r+b.
    {
        const float4* isrc = (const float4*)items;  // [b][NG*8] float4 per row
        #pragma unroll
        for (int i = 0; i < 8; i++) {
            int idx0 = t + i * 256;
            int grp = idx0 >> 10;
            int idx = idx0 & 1023;
            int b = (idx & 7) | ((idx >> 6) << 3);
            int q = ((idx >> 3) & 3) | (((idx >> 5) & 1) << 2);
            int g = 2 * bx + grp;
            float4 v = isrc[(size_t)b * (NGRP * 8) + (size_t)g * 8 + q];
            int r0 = 16 + 33 * grp + 4 * q;
            AsT[(r0 + 0) * PA + b] = v.x;
            AsT[(r0 + 1) * PA + b] = v.y;
            AsT[(r0 + 2) * PA + b] = v.z;
            AsT[(r0 + 3) * PA + b] = v.w;
        }
    }
    // W1d[g][j][c]: float4 = k-quad -> Ws4[cq][j].  phase: 8 consecutive j, quad=(cq+j)%8.
    {
        const float4* wsrc = (const float4*)W1d;   // g*256 + j*4 + cq
        #pragma unroll
        for (int i = 0; i < 2; i++) {
            int idx = t + i * 256;        // 0..511
            int j = idx & 127, cq = idx >> 7;
            int g = 2 * bx + (j >> 6), jl = j & 63;
            Ws4[cq * WQ + j] = wsrc[(size_t)g * 256 + jl * 4 + cq];
        }
    }
    // W1v[g][j][v]: float4 = k-quad -> Ws4[4+vq][j]. phase: j fixed, vq 0..7 -> quads distinct.
    {
        const float4* wsrc = (const float4*)W1v;   // g*512 + j*8 + vq
        #pragma unroll
        for (int i = 0; i < 4; i++) {
            int idx = t + i * 256;        // 0..1023
            int j = idx >> 3, vq = idx & 7;
            int g = 2 * bx + (j >> 6), jl = j & 63;
            Ws4[(4 + vq) * WQ + j] = wsrc[(size_t)g * 512 + jl * 8 + vq];
        }
    }
    // W2[g][o][j] -> W2sT[grp][j][o];  b1; b2.
    if (t < 128) {
        int grp = t >> 6, tt = t & 63;
        int o = tt >> 4, jq = tt & 15;
        const float4* wsrc = (const float4*)W2;    // g*64 + o*16 + jq
        float4 v = wsrc[(size_t)(2 * bx + grp) * 64 + o * 16 + jq];
        W2sT[grp * 256 + (4 * jq + 0) * 4 + o] = v.x;
        W2sT[grp * 256 + (4 * jq + 1) * 4 + o] = v.y;
        W2sT[grp * 256 + (4 * jq + 2) * 4 + o] = v.z;
        W2sT[grp * 256 + (4 * jq + 3) * 4 + o] = v.w;
    } else {
        int tt = t - 128;
        b1s[tt] = b1[(size_t)(2 * bx) * 64 + tt];
    }
    if (t < 8) b2s[t] = b2[(size_t)bx * 8 + t];
    __syncthreads();

    // ================= fc1 =================
    // t = bt*16 + jt.  jt = grp*8 + jt7.  thread j-set: grp*64 + jt7 + 8u (u 0..7).
    // b-set: b0..b0+7 (4 pairs).
    const int jt = t & 15, bt = t >> 4;
    const int grpf = jt >> 3, jt7 = jt & 7;
    const int b0 = bt * 8;
    const float* ArowI = AsT + (16 + 33 * grpf) * PA;  // items rows (k=16 maps here)
    const int jbase = grpf * 64 + jt7;

    ull acc[8][4];
    #pragma unroll
    for (int uu = 0; uu < 8; uu++)
        #pragma unroll
        for (int bp = 0; bp < 4; bp++) acc[uu][bp] = 0ULL;

    // --- day ks: kq 0..3 ---
    #pragma unroll 2
    for (int kq = 0; kq < 4; kq++) {
        float4 w4[8];
        #pragma unroll
        for (int uu = 0; uu < 8; uu++)
            w4[uu] = Ws4[kq * WQ + jbase + 8 * uu];
        #pragma unroll
        for (int kr = 0; kr < 4; kr++) {
            const float* ar = AsT + (kq * 4 + kr) * PA;
            ull a2[4];
            #pragma unroll
            for (int bp = 0; bp < 4; bp++)
                a2[bp] = *(const ull*)&ar[b0 + 2 * bp];
            #pragma unroll
            for (int uu = 0; uu < 8; uu++) {
                float wc = (kr == 0) ? w4[uu].x : (kr == 1) ? w4[uu].y
                         : (kr == 2) ? w4[uu].z : w4[uu].w;
                ull w2;
                PACK2(w2, wc);
                #pragma unroll
                for (int bp = 0; bp < 4; bp++)
                    FMA2(acc[uu][bp], a2[bp], w2, acc[uu][bp]);
            }
        }
    }
    // --- item ks: kq 4..11 ---
    #pragma unroll 2
    for (int kq = 4; kq < 12; kq++) {
        float4 w4[8];
        #pragma unroll
        for (int uu = 0; uu < 8; uu++)
            w4[uu] = Ws4[kq * WQ + jbase + 8 * uu];
        #pragma unroll
        for (int kr = 0; kr < 4; kr++) {
            const float* ar = ArowI + ((kq - 4) * 4 + kr) * PA;
            ull a2[4];
            #pragma unroll
            for (int bp = 0; bp < 4; bp++)
                a2[bp] = *(const ull*)&ar[b0 + 2 * bp];
            #pragma unroll
            for (int uu = 0; uu < 8; uu++) {
                float wc = (kr == 0) ? w4[uu].x : (kr == 1) ? w4[uu].y
                         : (kr == 2) ? w4[uu].z : w4[uu].w;
                ull w2;
                PACK2(w2, wc);
                #pragma unroll
                for (int bp = 0; bp < 4; bp++)
                    FMA2(acc[uu][bp], a2[bp], w2, acc[uu][bp]);
            }
        }
    }

    __syncthreads();   // everyone done reading AsT/Ws4

    // bias + relu; store hs[j][b], group-1 rows offset +2 floats.
    #pragma unroll
    for (int uu = 0; uu < 8; uu++) {
        int j = jbase + 8 * uu;
        float bias = b1s[j];
        float* hrow = hs + j * PA + 2 * grpf;
        #pragma unroll
        for (int bp = 0; bp < 4; bp++) {
            float lo, hi;
            UNPACK2(lo, hi, acc[uu][bp]);
            float2 st;
            st.x = fmaxf(lo + bias, 0.0f);
            st.y = fmaxf(hi + bias, 0.0f);
            *(float2*)&hrow[b0 + 2 * bp] = st;
        }
    }
    __syncthreads();

    // ================= fc2 =================
    {
        const int b = t & 127, grp2 = t >> 7;
        const float* hb = hs + grp2 * (64 * PA) + 2 * grp2 + b;
        const float* w2p = W2sT + grp2 * 256;
        ull y01 = *(const ull*)&b2s[grp2 * 4];
        ull y23 = *(const ull*)&b2s[grp2 * 4 + 2];
        #pragma unroll 8
        for (int j = 0; j < 64; j++) {
            float hv = hb[j * PA];
            ull hv2;
            PACK2(hv2, hv);
            ulonglong2 w = *(const ulonglong2*)&w2p[j * 4];
            FMA2(y01, hv2, w.x, y01);
            FMA2(y23, hv2, w.y, y23);
        }
        float4 res;
        UNPACK2(res.x, res.y, y01);
        UNPACK2(res.z, res.w, y23);
        int g = 2 * bx + grp2;
        *(float4*)&out[(size_t)b * (NGRP * 4) + (size_t)g * 4] = res;
    }
}

extern "C" void kernel_launch(void* const* d_in, const int* in_sizes, int n_in,
                              void* d_out, int out_size)
{
    const float* day   = (const float*)d_in[0];
    const float* items = (const float*)d_in[1];
    const float* W1d   = (const float*)d_in[2];
    const float* W1v   = (const float*)d_in[3];
    const float* b1    = (const float*)d_in[4];
    const float* W2    = (const float*)d_in[5];
    const float* b2    = (const float*)d_in[6];
    float* out = (float*)d_out;

    splitmlp_kernel<<<NGRP / 2, 256>>>(day, items, W1d, W1v, b1, W2, b2, out);
}

// round 7
// speedup vs baseline: 1.0377x; 1.0377x over previous
#include <cuda_runtime.h>

// SplitMLP R4: 1 group/CTA, warp tile 32b x 32j, thread tile 8b x 4j (32 acc regs),
// FFMA2 mainloop, L1-wavefront-minimized layouts.
//   AsT[k][b]  pitch 132 (LDS.128 a-loads: 1 wf)
//   Ws [k][j]  pitch 68  (LDS.128 w-load: 8 consecutive float4 = 1 wf, bt-broadcast)
//   hs [b][j]  pitch 68  (STS.128 / LDS.128 at 512B floor)

#define NG 10000
#define PA 132
#define WP 68
#define ASZ (48 * PA)          // 6336
#define USZ (ASZ + 48 * WP)    // 9600 floats (hs needs 128*68=8704 <= USZ)

#define FMA2(d, a, b, c) \
    asm("fma.rn.f32x2 %0, %1, %2, %3;" : "=l"(d) : "l"(a), "l"(b), "l"(c))
#define PACK2(d, x) \
    asm("mov.b64 %0, {%1, %1};" : "=l"(d) : "f"(x))
#define UNPACK2(lo, hi, v) \
    asm("mov.b64 {%0, %1}, %2;" : "=f"(lo), "=f"(hi) : "l"(v))

typedef unsigned long long ull;

__global__ __launch_bounds__(256, 3)
void splitmlp_kernel(const float* __restrict__ day,
                     const float* __restrict__ items,
                     const float* __restrict__ W1d,
                     const float* __restrict__ W1v,
                     const float* __restrict__ b1,
                     const float* __restrict__ W2,
                     const float* __restrict__ b2,
                     float* __restrict__ out)
{
    __shared__ __align__(16) float u[USZ];
    __shared__ __align__(16) float W2sT[64 * 4];   // [j][o]
    __shared__ float b1s[64];
    __shared__ __align__(16) float b2s[4];

    float* AsT = u;            // [k][b]
    float* Ws  = u + ASZ;      // [k][j]
    float* hs  = u;            // [b][j] after sync

    const int g = blockIdx.x;
    const int t = threadIdx.x;

    // ================= Staging =================
    // day[b][c] -> AsT[c][b]
    {
        const float4* dsrc = (const float4*)day;   // 512 float4
        #pragma unroll
        for (int i = 0; i < 2; i++) {
            int idx = t + i * 256;
            int b = idx >> 2, q = idx & 3;
            float4 v = dsrc[idx];
            AsT[(4 * q + 0) * PA + b] = v.x;
            AsT[(4 * q + 1) * PA + b] = v.y;
            AsT[(4 * q + 2) * PA + b] = v.z;
            AsT[(4 * q + 3) * PA + b] = v.w;
        }
    }
    // items[b][g][v] -> AsT[16+v][b].  per-warp 8b x 4q, <=2-way STS.
    {
        const float4* isrc = (const float4*)items;  // [b][NG*8]
        #pragma unroll
        for (int i = 0; i < 4; i++) {
            int idx = t + i * 256;                  // 0..1023
            int b = (idx & 7) | ((idx >> 6) << 3);
            int q = ((idx >> 3) & 3) | (((idx >> 5) & 1) << 2);
            float4 v = isrc[(size_t)b * (NG * 8) + (size_t)g * 8 + q];
            int r0 = 16 + 4 * q;
            AsT[(r0 + 0) * PA + b] = v.x;
            AsT[(r0 + 1) * PA + b] = v.y;
            AsT[(r0 + 2) * PA + b] = v.z;
            AsT[(r0 + 3) * PA + b] = v.w;
        }
    }
    // W1d[g][j][c] -> Ws[c][j]  (transpose, <=2-way STS)
    {
        const float4* wsrc = (const float4*)W1d;   // g*256 + j*4 + cq
        int j = t >> 2, cq = t & 3;
        float4 v = wsrc[(size_t)g * 256 + j * 4 + cq];
        Ws[(4 * cq + 0) * WP + j] = v.x;
        Ws[(4 * cq + 1) * WP + j] = v.y;
        Ws[(4 * cq + 2) * WP + j] = v.z;
        Ws[(4 * cq + 3) * WP + j] = v.w;
    }
    // W1v[g][j][v] -> Ws[16+v][j].  per-warp 8j x 4vq, <=2-way STS.
    {
        const float4* wsrc = (const float4*)W1v;   // g*512 + j*8 + vq
        #pragma unroll
        for (int i = 0; i < 2; i++) {
            int idx = t + i * 256;                 // 0..511
            int hi = idx >> 5;                     // warp-constant
            int j  = ((idx >> 2) & 7) | ((hi & 7) << 3);
            int vq = (idx & 3) | ((hi >> 3) << 2);
            float4 v = wsrc[(size_t)g * 512 + j * 8 + vq];
            int r0 = 16 + 4 * vq;
            Ws[(r0 + 0) * WP + j] = v.x;
            Ws[(r0 + 1) * WP + j] = v.y;
            Ws[(r0 + 2) * WP + j] = v.z;
            Ws[(r0 + 3) * WP + j] = v.w;
        }
    }
    // W2[g][o][j] -> W2sT[j][o];  b1; b2
    if (t < 64) {
        int o = t >> 4, jq = t & 15;
        const float4* wsrc = (const float4*)W2;    // g*64 + o*16 + jq
        float4 v = wsrc[(size_t)g * 64 + o * 16 + jq];
        W2sT[(4 * jq + 0) * 4 + o] = v.x;
        W2sT[(4 * jq + 1) * 4 + o] = v.y;
        W2sT[(4 * jq + 2) * 4 + o] = v.z;
        W2sT[(4 * jq + 3) * 4 + o] = v.w;
    } else if (t < 128) {
        b1s[t - 64] = b1[(size_t)g * 64 + (t - 64)];
    } else if (t < 132) {
        b2s[t - 128] = b2[(size_t)g * 4 + (t - 128)];
    }
    __syncthreads();

    // ================= fc1 =================
    const int lane = t & 31, warp = t >> 5;
    const int warpb = warp & 3, warpj = warp >> 2;
    const int bt4 = lane >> 3, jt8 = lane & 7;
    const int b0 = warpb * 32 + bt4 * 8;
    const int j0 = warpj * 32 + jt8 * 4;

    ull acc[4][4];   // [b-pair][j]
    #pragma unroll
    for (int bp = 0; bp < 4; bp++)
        #pragma unroll
        for (int jj = 0; jj < 4; jj++) acc[bp][jj] = 0ULL;

    const float* Arow = AsT + b0;
    const float* Wrow = Ws + j0;

    #pragma unroll 4
    for (int k = 0; k < 48; k++) {
        ulonglong2 A0 = *(const ulonglong2*)(Arow + k * PA);      // b0..b0+3
        ulonglong2 A1 = *(const ulonglong2*)(Arow + k * PA + 4);  // b0+4..b0+7
        float4 wv = *(const float4*)(Wrow + k * WP);
        ull w0, w1, w2, w3;
        PACK2(w0, wv.x); PACK2(w1, wv.y); PACK2(w2, wv.z); PACK2(w3, wv.w);
        FMA2(acc[0][0], A0.x, w0, acc[0][0]);
        FMA2(acc[0][1], A0.x, w1, acc[0][1]);
        FMA2(acc[0][2], A0.x, w2, acc[0][2]);
        FMA2(acc[0][3], A0.x, w3, acc[0][3]);
        FMA2(acc[1][0], A0.y, w0, acc[1][0]);
        FMA2(acc[1][1], A0.y, w1, acc[1][1]);
        FMA2(acc[1][2], A0.y, w2, acc[1][2]);
        FMA2(acc[1][3], A0.y, w3, acc[1][3]);
        FMA2(acc[2][0], A1.x, w0, acc[2][0]);
        FMA2(acc[2][1], A1.x, w1, acc[2][1]);
        FMA2(acc[2][2], A1.x, w2, acc[2][2]);
        FMA2(acc[2][3], A1.x, w3, acc[2][3]);
        FMA2(acc[3][0], A1.y, w0, acc[3][0]);
        FMA2(acc[3][1], A1.y, w1, acc[3][1]);
        FMA2(acc[3][2], A1.y, w2, acc[3][2]);
        FMA2(acc[3][3], A1.y, w3, acc[3][3]);
    }

    const float bias0 = b1s[j0 + 0];
    const float bias1 = b1s[j0 + 1];
    const float bias2 = b1s[j0 + 2];
    const float bias3 = b1s[j0 + 3];

    __syncthreads();   // everyone finished reading AsT/Ws before hs overwrite

    // bias + relu; store hs[b][j] as float4 over j (STS.128)
    #pragma unroll
    for (int bp = 0; bp < 4; bp++) {
        float l0, h0, l1, h1, l2, h2, l3, h3;
        UNPACK2(l0, h0, acc[bp][0]);
        UNPACK2(l1, h1, acc[bp][1]);
        UNPACK2(l2, h2, acc[bp][2]);
        UNPACK2(l3, h3, acc[bp][3]);
        float4 flo, fhi;
        flo.x = fmaxf(l0 + bias0, 0.0f);
        flo.y = fmaxf(l1 + bias1, 0.0f);
        flo.z = fmaxf(l2 + bias2, 0.0f);
        flo.w = fmaxf(l3 + bias3, 0.0f);
        fhi.x = fmaxf(h0 + bias0, 0.0f);
        fhi.y = fmaxf(h1 + bias1, 0.0f);
        fhi.z = fmaxf(h2 + bias2, 0.0f);
        fhi.w = fmaxf(h3 + bias3, 0.0f);
        *(float4*)&hs[(b0 + 2 * bp + 0) * WP + j0] = flo;
        *(float4*)&hs[(b0 + 2 * bp + 1) * WP + j0] = fhi;
    }
    __syncthreads();

    // ================= fc2 =================
    if (t < 128) {
        const int b = t;
        const float* hb = hs + b * WP;
        ull y01 = *(const ull*)&b2s[0];
        ull y23 = *(const ull*)&b2s[2];
        #pragma unroll 4
        for (int jq = 0; jq < 16; jq++) {
            float4 h4 = *(const float4*)(hb + jq * 4);
            #pragma unroll
            for (int jj = 0; jj < 4; jj++) {
                float hv = (jj == 0) ? h4.x : (jj == 1) ? h4.y : (jj == 2) ? h4.z : h4.w;
                ull hv2;
                PACK2(hv2, hv);
                ulonglong2 w = *(const ulonglong2*)&W2sT[(4 * jq + jj) * 4];
                FMA2(y01, hv2, w.x, y01);
                FMA2(y23, hv2, w.y, y23);
            }
        }
        float4 res;
        UNPACK2(res.x, res.y, y01);
        UNPACK2(res.z, res.w, y23);
        *(float4*)&out[(size_t)b * (NG * 4) + (size_t)g * 4] = res;
    }
}

extern "C" void kernel_launch(void* const* d_in, const int* in_sizes, int n_in,
                              void* d_out, int out_size)
{
    const float* day   = (const float*)d_in[0];
    const float* items = (const float*)d_in[1];
    const float* W1d   = (const float*)d_in[2];
    const float* W1v   = (const float*)d_in[3];
    const float* b1    = (const float*)d_in[4];
    const float* W2    = (const float*)d_in[5];
    const float* b2    = (const float*)d_in[6];
    float* out = (float*)d_out;

    splitmlp_kernel<<<NG, 256>>>(day, items, W1d, W1v, b1, W2, b2, out);
}

// round 10
// speedup vs baseline: 2.5488x; 2.4563x over previous
#include <cuda_runtime.h>
#include <cstdint>

// SplitMLP R10: fc1 on legacy tensor-core mma.sync (tf32, m16n8k8), fc2 in regs.
//   As[b][k] pitch 52 (row-major), Ws[j][k] pitch 52 — pitch 52 => 20r+c bank map,
//   conflict-free scalar fragment loads AND floor-rate STS.128 staging (no transpose).
//   4 warps: warp w owns b-rows 32w..32w+31 (2 m-tiles) x all 64 j (8 n-tiles).
//   D fragments -> bias+relu+fc2 partials in regs -> quad shfl.bfly reduce -> STG.

#define NG 10000
#define PA 52

typedef unsigned long long ull;
typedef unsigned int uint;

#define FMA2(d, a, b, c) \
    asm("fma.rn.f32x2 %0, %1, %2, %3;" : "=l"(d) : "l"(a), "l"(b), "l"(c))
#define ADD2(d, a, b) \
    asm("add.rn.f32x2 %0, %1, %2;" : "=l"(d) : "l"(a), "l"(b))
#define PACK2(d, x) \
    asm("mov.b64 %0, {%1, %1};" : "=l"(d) : "f"(x))
#define UNPACK2(lo, hi, v) \
    asm("mov.b64 {%0, %1}, %2;" : "=f"(lo), "=f"(hi) : "l"(v))

__device__ __forceinline__ float totf32(float x) {
    float r;
    asm("cvt.rna.tf32.f32 %0, %1;" : "=f"(r) : "f"(x));
    return r;
}
__device__ __forceinline__ float4 totf324(float4 v) {
    v.x = totf32(v.x); v.y = totf32(v.y); v.z = totf32(v.z); v.w = totf32(v.w);
    return v;
}

__device__ __forceinline__ void mma_tf32(float& d0, float& d1, float& d2, float& d3,
                                         uint a0, uint a1, uint a2, uint a3,
                                         uint b0, uint b1) {
    asm volatile(
        "mma.sync.aligned.m16n8k8.row.col.f32.tf32.tf32.f32 "
        "{%0,%1,%2,%3}, {%4,%5,%6,%7}, {%8,%9}, {%0,%1,%2,%3};"
        : "+f"(d0), "+f"(d1), "+f"(d2), "+f"(d3)
        : "r"(a0), "r"(a1), "r"(a2), "r"(a3), "r"(b0), "r"(b1));
}

__device__ __forceinline__ ull bfly_add2(ull v, int m) {
    float lo, hi;
    UNPACK2(lo, hi, v);
    uint lo2 = __shfl_xor_sync(0xffffffffu, __float_as_uint(lo), m);
    uint hi2 = __shfl_xor_sync(0xffffffffu, __float_as_uint(hi), m);
    ull o;
    asm("mov.b64 %0, {%1, %2};" : "=l"(o) : "r"(lo2), "r"(hi2));
    ull r;
    ADD2(r, v, o);
    return r;
}

__global__ __launch_bounds__(128)
void splitmlp_kernel(const float* __restrict__ day,
                     const float* __restrict__ items,
                     const float* __restrict__ W1d,
                     const float* __restrict__ W1v,
                     const float* __restrict__ b1,
                     const float* __restrict__ W2,
                     const float* __restrict__ b2,
                     float* __restrict__ out)
{
    __shared__ __align__(16) float As[128 * PA];   // [b][k], k 0..47 valid
    __shared__ __align__(16) float Ws[64 * PA];    // [j][k]
    __shared__ __align__(16) float W2sT[64 * 4];   // [j][o]
    __shared__ __align__(16) float b1s[64];
    __shared__ __align__(16) float b2s[4];

    const int g = blockIdx.x;
    const int t = threadIdx.x;
    const int lane = t & 31, w = t >> 5;

    // ================= Staging (tf32-rounded where MMA consumes) =================
    // day[b][c] -> As[b][4q..4q+3]
    {
        const float4* src = (const float4*)day;    // 512 float4
        #pragma unroll
        for (int i = 0; i < 4; i++) {
            int idx = t + i * 128;
            int b = idx >> 2, q = idx & 3;
            *(float4*)&As[b * PA + 4 * q] = totf324(src[idx]);
        }
    }
    // items[b][g][v] -> As[b][16+4q]
    {
        const float4* src = (const float4*)items;  // [b][NG*8]
        #pragma unroll
        for (int i = 0; i < 8; i++) {
            int idx = t + i * 128;
            int b = idx >> 3, q = idx & 7;
            float4 v = src[(size_t)b * (NG * 8) + (size_t)g * 8 + q];
            *(float4*)&As[b * PA + 16 + 4 * q] = totf324(v);
        }
    }
    // W1d[g][j][c] -> Ws[j][4cq]
    {
        const float4* src = (const float4*)W1d;    // g*256 + j*4 + cq
        #pragma unroll
        for (int i = 0; i < 2; i++) {
            int idx = t + i * 128;
            int j = idx >> 2, cq = idx & 3;
            *(float4*)&Ws[j * PA + 4 * cq] = totf324(src[(size_t)g * 256 + j * 4 + cq]);
        }
    }
    // W1v[g][j][v] -> Ws[j][16+4vq]
    {
        const float4* src = (const float4*)W1v;    // g*512 + j*8 + vq
        #pragma unroll
        for (int i = 0; i < 4; i++) {
            int idx = t + i * 128;
            int j = idx >> 3, vq = idx & 7;
            *(float4*)&Ws[j * PA + 16 + 4 * vq] = totf324(src[(size_t)g * 512 + j * 8 + vq]);
        }
    }
    // W2[g][o][j] -> W2sT[j][o]; b1; b2  (full fp32)
    if (t < 64) {
        int o = t >> 4, jq = t & 15;
        float4 v = ((const float4*)W2)[(size_t)g * 64 + o * 16 + jq];
        W2sT[(4 * jq + 0) * 4 + o] = v.x;
        W2sT[(4 * jq + 1) * 4 + o] = v.y;
        W2sT[(4 * jq + 2) * 4 + o] = v.z;
        W2sT[(4 * jq + 3) * 4 + o] = v.w;
    } else {
        b1s[t - 64] = b1[(size_t)g * 64 + (t - 64)];
    }
    if (t < 4) b2s[t] = b2[(size_t)g * 4 + t];
    __syncthreads();

    // ================= fc1: mma.sync tf32 =================
    const int r = lane >> 2, q = lane & 3;
    const uint* Au = (const uint*)As;
    const uint* Wu = (const uint*)Ws;
    const int m0 = w * 32;            // warp's first b-row; m-tiles at m0, m0+16

    float d[2][8][4];
    #pragma unroll
    for (int mt = 0; mt < 2; mt++)
        #pragma unroll
        for (int nt = 0; nt < 8; nt++)
            #pragma unroll
            for (int c = 0; c < 4; c++) d[mt][nt][c] = 0.0f;

    #pragma unroll
    for (int ks = 0; ks < 6; ks++) {
        const int k0 = ks * 8;
        // B fragments: b0 = W(k0+q, j = nt*8 + r), b1 = W(k0+4+q, same j)
        uint bf[8][2];
        #pragma unroll
        for (int nt = 0; nt < 8; nt++) {
            bf[nt][0] = Wu[(nt * 8 + r) * PA + k0 + q];
            bf[nt][1] = Wu[(nt * 8 + r) * PA + k0 + 4 + q];
        }
        // A fragments per m-tile: a0=(row, k0+q) a1=(row+8,..) a2=(row, k0+4+q) a3=(row+8,..)
        #pragma unroll
        for (int mt = 0; mt < 2; mt++) {
            const int row = m0 + mt * 16 + r;
            uint a0 = Au[row * PA + k0 + q];
            uint a1 = Au[(row + 8) * PA + k0 + q];
            uint a2 = Au[row * PA + k0 + 4 + q];
            uint a3 = Au[(row + 8) * PA + k0 + 4 + q];
            #pragma unroll
            for (int nt = 0; nt < 8; nt++)
                mma_tf32(d[mt][nt][0], d[mt][nt][1], d[mt][nt][2], d[mt][nt][3],
                         a0, a1, a2, a3, bf[nt][0], bf[nt][1]);
        }
    }

    // ================= bias + relu + fc2 (registers) =================
    // Thread holds rows {m0+mt*16+r, +8}, cols {nt*8+2q, +1}.
    // Partial y for 4 rows: idx = mt*2 + (0:row r | 1:row r+8)
    ull y01[4], y23[4];
    #pragma unroll
    for (int i = 0; i < 4; i++) { y01[i] = 0ULL; y23[i] = 0ULL; }

    #pragma unroll
    for (int nt = 0; nt < 8; nt++) {
        const int j0 = nt * 8 + 2 * q;
        float2 bb = *(const float2*)&b1s[j0];
        ulonglong2 wj0 = *(const ulonglong2*)&W2sT[j0 * 4];
        ulonglong2 wj1 = *(const ulonglong2*)&W2sT[(j0 + 1) * 4];
        #pragma unroll
        for (int mt = 0; mt < 2; mt++) {
            // low row (r): cols j0, j0+1 = c0, c1
            {
                float h0 = fmaxf(d[mt][nt][0] + bb.x, 0.0f);
                float h1 = fmaxf(d[mt][nt][1] + bb.y, 0.0f);
                ull h;
                PACK2(h, h0);
                FMA2(y01[mt * 2], h, wj0.x, y01[mt * 2]);
                FMA2(y23[mt * 2], h, wj0.y, y23[mt * 2]);
                PACK2(h, h1);
                FMA2(y01[mt * 2], h, wj1.x, y01[mt * 2]);
                FMA2(y23[mt * 2], h, wj1.y, y23[mt * 2]);
            }
            // high row (r+8): c2, c3
            {
                float h0 = fmaxf(d[mt][nt][2] + bb.x, 0.0f);
                float h1 = fmaxf(d[mt][nt][3] + bb.y, 0.0f);
                ull h;
                PACK2(h, h0);
                FMA2(y01[mt * 2 + 1], h, wj0.x, y01[mt * 2 + 1]);
                FMA2(y23[mt * 2 + 1], h, wj0.y, y23[mt * 2 + 1]);
                PACK2(h, h1);
                FMA2(y01[mt * 2 + 1], h, wj1.x, y01[mt * 2 + 1]);
                FMA2(y23[mt * 2 + 1], h, wj1.y, y23[mt * 2 + 1]);
            }
        }
    }

    // quad reduction (lanes 4r..4r+3 share the same rows)
    #pragma unroll
    for (int i = 0; i < 4; i++) {
        y01[i] = bfly_add2(y01[i], 1);
        y01[i] = bfly_add2(y01[i], 2);
        y23[i] = bfly_add2(y23[i], 1);
        y23[i] = bfly_add2(y23[i], 2);
    }

    // lane q writes row-set q: b = m0 + (q>>1)*16 + (q&1)*8 + r
    {
        ull s01 = (q == 0) ? y01[0] : (q == 1) ? y01[1] : (q == 2) ? y01[2] : y01[3];
        ull s23 = (q == 0) ? y23[0] : (q == 1) ? y23[1] : (q == 2) ? y23[2] : y23[3];
        ull bb01 = *(const ull*)&b2s[0];
        ull bb23 = *(const ull*)&b2s[2];
        ADD2(s01, s01, bb01);
        ADD2(s23, s23, bb23);
        float4 res;
        UNPACK2(res.x, res.y, s01);
        UNPACK2(res.z, res.w, s23);
        const int b = m0 + (q >> 1) * 16 + (q & 1) * 8 + r;
        *(float4*)&out[(size_t)b * (NG * 4) + (size_t)g * 4] = res;
    }
}

extern "C" void kernel_launch(void* const* d_in, const int* in_sizes, int n_in,
                              void* d_out, int out_size)
{
    const float* day   = (const float*)d_in[0];
    const float* items = (const float*)d_in[1];
    const float* W1d   = (const float*)d_in[2];
    const float* W1v   = (const float*)d_in[3];
    const float* b1    = (const float*)d_in[4];
    const float* W2    = (const float*)d_in[5];
    const float* b2    = (const float*)d_in[6];
    float* out = (float*)d_out;

    splitmlp_kernel<<<NG, 128>>>(day, items, W1d, W1v, b1, W2, b2, out);
}